// round 14
// baseline (speedup 1.0000x reference)
#include <cuda_runtime.h>
#include <cstdint>

// Self_attention: out = softmax(QK^T/sqrt(S) + cauchy_bias, causal) @ V
// B=8, S=2048, D=512, fp32. Flash-attention, tf32 mma.sync, O in registers.
// R11 base + (1) __fdividef bias (MUFU.RCP, not div.rn slow path),
// (2) V commits decoupled from QK critical wait (wait_group 1),
// (3) batch-major grid for L2 K/V locality (heavy-first within batch).
// QK raw fp32 operands (HW tf32 trunc); P RNA tf32; V raw. Fixed-shift softmax.

#define B_   8
#define S_   2048
#define D_   512
#define BM   64
#define BN   64
#define DC   64
#define NDC  8
#define QP   72     // Q/K chunk pitch  (==8 mod 32 -> conflict-free LDS.64 frags)
#define PP   72     // P tile pitch     (==8 mod 32)
#define VPW  520    // V resident pitch (==8 mod 32)
#define NT   512
#define MSH  6.0f

#define CP_COMMIT() asm volatile("cp.async.commit_group;\n" ::: "memory")
#define CP_WAIT(n)  asm volatile("cp.async.wait_group %0;\n" :: "n"(n) : "memory")

__device__ __forceinline__ float f2tf(float x) {
    uint32_t u;
    asm("cvt.rna.tf32.f32 %0, %1;" : "=r"(u) : "f"(x));
    return __uint_as_float(u);
}

__device__ __forceinline__ void mma8(float& c0, float& c1, float& c2, float& c3,
                                     float a0, float a1, float a2, float a3,
                                     float b0, float b1) {
    asm volatile(
        "mma.sync.aligned.m16n8k8.row.col.f32.tf32.tf32.f32 "
        "{%0,%1,%2,%3},{%4,%5,%6,%7},{%8,%9},{%0,%1,%2,%3};"
        : "+f"(c0), "+f"(c1), "+f"(c2), "+f"(c3)
        : "r"(__float_as_uint(a0)), "r"(__float_as_uint(a1)),
          "r"(__float_as_uint(a2)), "r"(__float_as_uint(a3)),
          "r"(__float_as_uint(b0)), "r"(__float_as_uint(b1)));
}

__device__ __forceinline__ void cp64(float* dst, int pitch, const float* src, int tid) {
#pragma unroll
    for (int it = 0; it < 2; ++it) {
        int idx = tid + it * NT;
        int r   = idx >> 4;
        int c4  = (idx & 15) << 2;
        uint32_t da = (uint32_t)__cvta_generic_to_shared(dst + r * pitch + c4);
        asm volatile("cp.async.cg.shared.global [%0], [%1], 16;\n"
                     :: "r"(da), "l"(src + (size_t)r * D_ + c4) : "memory");
    }
}

__global__ void __launch_bounds__(NT, 1)
attn_tf32_kernel(const float* __restrict__ Q, const float* __restrict__ K,
                 const float* __restrict__ V, float* __restrict__ Oout) {
    extern __shared__ float sm[];
    float* Vsm = sm;                       // [64][520]
    float* Qb  = Vsm + BM * VPW;           // 2 x [64][72]
    float* Kb  = Qb + 2 * BM * QP;         // 2 x [64][72]
    float* PB  = Kb + 2 * BM * QP;         // [64][72]
    float* SB  = PB + BM * PP;             // 512 floats

    const int tid  = threadIdx.x;
    const int lane = tid & 31;
    const int warp = tid >> 5;
    const int g    = lane >> 2;
    const int tg   = lane & 3;
    const int wr   = warp & 3;             // QK row group
    const int wq   = warp >> 2;            // QK col group
    const int rb   = wr * 16;
    const int mh   = warp & 1;             // PV row half
    const int cs   = warp >> 1;            // PV col strip
    const int p0   = ((tg & 1) << 2) | (tg >> 1);

    const int bid = blockIdx.x;
    const int b   = bid >> 5;                    // batch-major: L2 K/V locality
    const int qb  = (S_ / BM - 1) - (bid & 31);  // heavy blocks first within batch

    const float* Qg = Q + ((size_t)b * S_ + (size_t)qb * BM) * D_;
    const float* Kg = K + (size_t)b * S_ * D_;
    const float* Vg = V + (size_t)b * S_ * D_;
    float*       Og = Oout + ((size_t)b * S_ + (size_t)qb * BM) * D_;

    float l0 = 0.f, l1 = 0.f;
    const float scale = 0.0220970869120796f;  // 1/sqrt(2048)
    const int i0 = qb * BM + rb + g;
    const int i1 = i0 + 8;

    float o[16][4];
#pragma unroll
    for (int t = 0; t < 16; ++t) { o[t][0]=0.f; o[t][1]=0.f; o[t][2]=0.f; o[t][3]=0.f; }

    // ---- prologue: prime Q0/K0 for kvb 0 ----
    cp64(Qb, QP, Qg, tid);
    cp64(Kb, QP, Kg, tid);
    CP_COMMIT();

    for (int kvb = 0; kvb <= qb; ++kvb) {
        const float* Kgb = Kg + (size_t)kvb * BN * D_;
        const float* Vgb = Vg + (size_t)kvb * BN * D_;

        float c[2][4];
        c[0][0]=0.f;c[0][1]=0.f;c[0][2]=0.f;c[0][3]=0.f;
        c[1][0]=0.f;c[1][1]=0.f;c[1][2]=0.f;c[1][3]=0.f;
        const bool live = !(kvb == qb && wq > wr);

        // ---- phase 1: S = Q K^T, 8 d-chunks; V commits decoupled (wait_group 1) ----
#pragma unroll
        for (int dc = 0; dc < NDC; ++dc) {
            if (dc == 0) { CP_WAIT(0); } else { CP_WAIT(1); }  // QK(dc) landed; V(dc-1) may lag
            __syncthreads();
            if (dc < 7) {
                int nb = (dc + 1) & 1;
                cp64(Qb + nb * BM * QP, QP, Qg + (dc + 1) * DC, tid);
                cp64(Kb + nb * BM * QP, QP, Kgb + (dc + 1) * DC, tid);
                CP_COMMIT();                                   // QK group (older)
                cp64(Vsm + dc * DC, VPW, Vgb + dc * DC, tid);
                CP_COMMIT();                                   // V group (newest)
            } else {
                cp64(Vsm + 7 * DC, VPW, Vgb + 7 * DC, tid);
                CP_COMMIT();
            }
            if (live) {
                const float* Qs = Qb + (dc & 1) * BM * QP;
                const float* Ks = Kb + (dc & 1) * BM * QP;
#pragma unroll
                for (int kk = 0; kk < 8; ++kk) {
                    const float* qr = Qs + (rb + g) * QP + kk * 8 + 2 * tg;
                    float2 qa  = *reinterpret_cast<const float2*>(qr);
                    float2 qb2 = *reinterpret_cast<const float2*>(qr + 8 * QP);
#pragma unroll
                    for (int nt = 0; nt < 2; ++nt) {
                        float2 kb = *reinterpret_cast<const float2*>(
                            Ks + (wq * 16 + nt * 8 + g) * QP + kk * 8 + 2 * tg);
                        mma8(c[nt][0], c[nt][1], c[nt][2], c[nt][3],
                             qa.x, qb2.x, qa.y, qb2.y, kb.x, kb.y);
                    }
                }
            }
        }

        // ---- phase 2: bias + mask + exp(s - M); accumulate row sums ----
        const int jb = kvb * BN + wq * 16;
#pragma unroll
        for (int nt = 0; nt < 2; ++nt) {
#pragma unroll
            for (int kq = 0; kq < 4; ++kq) {
                int i = (kq < 2) ? i0 : i1;
                int j = jb + nt * 8 + 2 * tg + (kq & 1);
                float p;
                if (j > i) {
                    p = 0.f;
                } else {
                    float d = (float)(i - j);
                    float bias = __fdividef(1.f, fmaf(0.2f * d, d, 1.f));  // MUFU.RCP
                    float s = c[nt][kq] * scale + bias;
                    p = __expf(s - MSH);
                }
                c[nt][kq] = p;
                if (kq < 2) l0 += p; else l1 += p;
            }
        }

        // ---- phase 3: P -> smem (tf32 RNA, pair-permuted) ----
#pragma unroll
        for (int nt = 0; nt < 2; ++nt) {
            int colb = wq * 16 + nt * 8 + p0;
            float* r0 = PB + (rb + g) * PP + colb;
            float* r1 = PB + (rb + g + 8) * PP + colb;
            r0[0] = f2tf(c[nt][0]);
            r0[2] = f2tf(c[nt][1]);
            r1[0] = f2tf(c[nt][2]);
            r1[2] = f2tf(c[nt][3]);
        }

        // prefetch Q0/K0 of next kvb into dead buf0 (lands during PV)
        CP_WAIT(0);    // all V chunks landed
        {
            int nkvb = (kvb < qb) ? kvb + 1 : kvb;
            cp64(Qb, QP, Qg, tid);
            cp64(Kb, QP, Kg + (size_t)nkvb * BN * D_, tid);
            CP_COMMIT();
        }
        __syncthreads();   // P and V all visible

        // ---- phase 4: O += P V (V resident; warp = 32 rows x 64 cols) ----
#pragma unroll
        for (int kk = 0; kk < 8; ++kk) {
            float2 pa[2], pb2[2];
#pragma unroll
            for (int mt = 0; mt < 2; ++mt) {
                const float* pr = PB + (mh * 32 + mt * 16 + g) * PP + kk * 8 + 2 * tg;
                pa[mt]  = *reinterpret_cast<const float2*>(pr);
                pb2[mt] = *reinterpret_cast<const float2*>(pr + 8 * PP);
            }
            const float* vrow = Vsm + (kk * 8 + tg) * VPW + cs * 64 + g;
#pragma unroll
            for (int nt = 0; nt < 8; ++nt) {
                float b0 = vrow[nt * 8];
                float b1 = vrow[nt * 8 + 4 * VPW];
#pragma unroll
                for (int mt = 0; mt < 2; ++mt) {
                    mma8(o[mt * 8 + nt][0], o[mt * 8 + nt][1],
                         o[mt * 8 + nt][2], o[mt * 8 + nt][3],
                         pa[mt].x, pb2[mt].x, pa[mt].y, pb2[mt].y, b0, b1);
                }
            }
        }
    }

    // ---- epilogue: reduce l, broadcast inverses, out = O * inv ----
    l0 += __shfl_xor_sync(0xffffffffu, l0, 1);
    l0 += __shfl_xor_sync(0xffffffffu, l0, 2);
    l1 += __shfl_xor_sync(0xffffffffu, l1, 1);
    l1 += __shfl_xor_sync(0xffffffffu, l1, 2);
    __syncthreads();
    if (tg == 0) {
        SB[wq * 64 + rb + g]     = l0;
        SB[wq * 64 + rb + g + 8] = l1;
    }
    __syncthreads();
    if (wq == 0) {
        float s0 = 0.f, s1 = 0.f;
#pragma unroll
        for (int q = 0; q < 4; ++q) {
            s0 += SB[q * 64 + rb + g];
            s1 += SB[q * 64 + rb + g + 8];
        }
        if (tg == 0) {
            SB[256 + rb + g]     = 1.0f / s0;
            SB[256 + rb + g + 8] = 1.0f / s1;
        }
    }
    __syncthreads();
#pragma unroll
    for (int mt = 0; mt < 2; ++mt) {
        int r0 = mh * 32 + mt * 16 + g;
        int r1 = r0 + 8;
        float invA = SB[256 + r0];
        float invB = SB[256 + r1];
#pragma unroll
        for (int nt = 0; nt < 8; ++nt) {
            int col = cs * 64 + nt * 8 + 2 * tg;
            *reinterpret_cast<float2*>(Og + (size_t)r0 * D_ + col) =
                make_float2(o[mt * 8 + nt][0] * invA, o[mt * 8 + nt][1] * invA);
            *reinterpret_cast<float2*>(Og + (size_t)r1 * D_ + col) =
                make_float2(o[mt * 8 + nt][2] * invB, o[mt * 8 + nt][3] * invB);
        }
    }
}

extern "C" void kernel_launch(void* const* d_in, const int* in_sizes, int n_in,
                              void* d_out, int out_size) {
    (void)in_sizes; (void)n_in; (void)out_size;
    const float* Q = (const float*)d_in[0];
    const float* K = (const float*)d_in[1];
    const float* V = (const float*)d_in[2];
    float* O = (float*)d_out;

    const size_t smem = (size_t)(BM * VPW + 4 * BM * QP + BM * PP + 512) * sizeof(float); // 227328
    cudaFuncSetAttribute(attn_tf32_kernel,
                         cudaFuncAttributeMaxDynamicSharedMemorySize, (int)smem);

    attn_tf32_kernel<<<S_ / BM * B_, NT, smem>>>(Q, K, V, O);
}

// round 15
// speedup vs baseline: 1.4169x; 1.4169x over previous
#include <cuda_runtime.h>
#include <cstdint>

// Self_attention: out = softmax(QK^T/sqrt(S) + cauchy_bias, causal) @ V
// B=8, S=2048, D=512, fp32. Flash-attention, tf32 mma.sync, O in registers.
// == R11 (364us) with ONE change: Cauchy bias via __fdividef (MUFU.RCP)
// instead of IEEE div.rn slow path. Everything else byte-identical.
// Fixed-shift softmax (exact). k-relabeled LDS.64 Q/K fragments.
// PV warps 32x64. QK raw fp32 operands (HW tf32 trunc); P RNA tf32; V raw.

#define B_   8
#define S_   2048
#define D_   512
#define BM   64
#define BN   64
#define DC   64
#define NDC  8
#define QP   72     // Q/K chunk pitch  (==8 mod 32 -> conflict-free LDS.64 frags)
#define PP   72     // P tile pitch     (==8 mod 32)
#define VPW  520    // V resident pitch (==8 mod 32)
#define NT   512
#define MSH  6.0f

#define CP_COMMIT() asm volatile("cp.async.commit_group;\n" ::: "memory")
#define CP_WAIT0()  asm volatile("cp.async.wait_group 0;\n" ::: "memory")

__device__ __forceinline__ float f2tf(float x) {
    uint32_t u;
    asm("cvt.rna.tf32.f32 %0, %1;" : "=r"(u) : "f"(x));
    return __uint_as_float(u);
}

__device__ __forceinline__ void mma8(float& c0, float& c1, float& c2, float& c3,
                                     float a0, float a1, float a2, float a3,
                                     float b0, float b1) {
    asm volatile(
        "mma.sync.aligned.m16n8k8.row.col.f32.tf32.tf32.f32 "
        "{%0,%1,%2,%3},{%4,%5,%6,%7},{%8,%9},{%0,%1,%2,%3};"
        : "+f"(c0), "+f"(c1), "+f"(c2), "+f"(c3)
        : "r"(__float_as_uint(a0)), "r"(__float_as_uint(a1)),
          "r"(__float_as_uint(a2)), "r"(__float_as_uint(a3)),
          "r"(__float_as_uint(b0)), "r"(__float_as_uint(b1)));
}

__device__ __forceinline__ void cp64(float* dst, int pitch, const float* src, int tid) {
#pragma unroll
    for (int it = 0; it < 2; ++it) {
        int idx = tid + it * NT;
        int r   = idx >> 4;
        int c4  = (idx & 15) << 2;
        uint32_t da = (uint32_t)__cvta_generic_to_shared(dst + r * pitch + c4);
        asm volatile("cp.async.cg.shared.global [%0], [%1], 16;\n"
                     :: "r"(da), "l"(src + (size_t)r * D_ + c4) : "memory");
    }
}

__global__ void __launch_bounds__(NT, 1)
attn_tf32_kernel(const float* __restrict__ Q, const float* __restrict__ K,
                 const float* __restrict__ V, float* __restrict__ Oout) {
    extern __shared__ float sm[];
    float* Vsm = sm;                       // [64][520]
    float* Qb  = Vsm + BM * VPW;           // 2 x [64][72]
    float* Kb  = Qb + 2 * BM * QP;         // 2 x [64][72]
    float* PB  = Kb + 2 * BM * QP;         // [64][72]
    float* SB  = PB + BM * PP;             // 512 floats

    const int tid  = threadIdx.x;
    const int lane = tid & 31;
    const int warp = tid >> 5;
    const int g    = lane >> 2;
    const int tg   = lane & 3;
    const int wr   = warp & 3;             // QK row group (16 rows)
    const int wq   = warp >> 2;            // QK col group
    const int rb   = wr * 16;
    const int mh   = warp & 1;             // PV row half (32 rows)
    const int cs   = warp >> 1;            // PV col strip (64 cols)
    const int p0   = ((tg & 1) << 2) | (tg >> 1);   // perm slot of col 2tg

    const int bid = blockIdx.x;
    const int b   = bid & 7;
    const int qb  = (S_ / BM - 1) - (bid >> 3);   // heavy blocks in wave 1

    const float* Qg = Q + ((size_t)b * S_ + (size_t)qb * BM) * D_;
    const float* Kg = K + (size_t)b * S_ * D_;
    const float* Vg = V + (size_t)b * S_ * D_;
    float*       Og = Oout + ((size_t)b * S_ + (size_t)qb * BM) * D_;

    float l0 = 0.f, l1 = 0.f;              // per-thread partial row sums
    const float scale = 0.0220970869120796f;  // 1/sqrt(2048)
    const int i0 = qb * BM + rb + g;
    const int i1 = i0 + 8;

    float o[16][4];
#pragma unroll
    for (int t = 0; t < 16; ++t) {
        o[t][0] = 0.f; o[t][1] = 0.f; o[t][2] = 0.f; o[t][3] = 0.f;
    }

    // ---- prologue: prime Q0/K0 for kvb 0 ----
    cp64(Qb, QP, Qg, tid);
    cp64(Kb, QP, Kg, tid);
    CP_COMMIT();

    for (int kvb = 0; kvb <= qb; ++kvb) {
        const float* Kgb = Kg + (size_t)kvb * BN * D_;
        const float* Vgb = Vg + (size_t)kvb * BN * D_;

        float c[2][4];
        c[0][0]=0.f;c[0][1]=0.f;c[0][2]=0.f;c[0][3]=0.f;
        c[1][0]=0.f;c[1][1]=0.f;c[1][2]=0.f;c[1][3]=0.f;

        const bool live = !(kvb == qb && wq > wr);

        // ---- phase 1: S = Q K^T, 8 d-chunks; V(dc) rides at dc ----
#pragma unroll
        for (int dc = 0; dc < NDC; ++dc) {
            CP_WAIT0();
            __syncthreads();               // chunk dc visible; prev buffers free
            if (dc + 1 < NDC) {
                int nb = (dc + 1) & 1;
                cp64(Qb + nb * BM * QP, QP, Qg + (dc + 1) * DC, tid);
                cp64(Kb + nb * BM * QP, QP, Kgb + (dc + 1) * DC, tid);
                cp64(Vsm + dc * DC, VPW, Vgb + dc * DC, tid);
            } else {
                cp64(Vsm + 7 * DC, VPW, Vgb + 7 * DC, tid);   // lands under phase 2
            }
            CP_COMMIT();
            if (live) {
                const float* Qs = Qb + (dc & 1) * BM * QP;
                const float* Ks = Kb + (dc & 1) * BM * QP;
#pragma unroll
                for (int kk = 0; kk < 8; ++kk) {
                    // k-relabel: MMA slots (tg, tg+4) fed with physical k = (2tg, 2tg+1)
                    const float* qr = Qs + (rb + g) * QP + kk * 8 + 2 * tg;
                    float2 qa  = *reinterpret_cast<const float2*>(qr);           // a0,a2
                    float2 qb2 = *reinterpret_cast<const float2*>(qr + 8 * QP);  // a1,a3
#pragma unroll
                    for (int nt = 0; nt < 2; ++nt) {
                        float2 kb = *reinterpret_cast<const float2*>(
                            Ks + (wq * 16 + nt * 8 + g) * QP + kk * 8 + 2 * tg); // b0,b1
                        mma8(c[nt][0], c[nt][1], c[nt][2], c[nt][3],
                             qa.x, qb2.x, qa.y, qb2.y, kb.x, kb.y);
                    }
                }
            }
        }

        // ---- phase 2: bias + mask + exp(s - M); accumulate row sums ----
        const int jb = kvb * BN + wq * 16;
#pragma unroll
        for (int nt = 0; nt < 2; ++nt) {
#pragma unroll
            for (int kq = 0; kq < 4; ++kq) {
                int i = (kq < 2) ? i0 : i1;
                int j = jb + nt * 8 + 2 * tg + (kq & 1);
                float p;
                if (j > i) {
                    p = 0.f;
                } else {
                    float d = (float)(i - j);
                    float bias = __fdividef(1.f, fmaf(0.2f * d, d, 1.f));  // MUFU.RCP
                    float s = c[nt][kq] * scale + bias;
                    p = __expf(s - MSH);
                }
                c[nt][kq] = p;
                if (kq < 2) l0 += p; else l1 += p;
            }
        }

        // ---- phase 3: P -> smem (tf32 RNA, pair-permuted) ----
#pragma unroll
        for (int nt = 0; nt < 2; ++nt) {
            int colb = wq * 16 + nt * 8 + p0;
            float* r0 = PB + (rb + g) * PP + colb;
            float* r1 = PB + (rb + g + 8) * PP + colb;
            r0[0] = f2tf(c[nt][0]);
            r0[2] = f2tf(c[nt][1]);
            r1[0] = f2tf(c[nt][2]);
            r1[2] = f2tf(c[nt][3]);
        }

        // prefetch Q0/K0 of next kvb into dead buf0 (lands during PV)
        CP_WAIT0();    // V chunk 7 landed
        {
            int nkvb = (kvb < qb) ? kvb + 1 : kvb;
            cp64(Qb, QP, Qg, tid);
            cp64(Kb, QP, Kg + (size_t)nkvb * BN * D_, tid);
            CP_COMMIT();
        }
        __syncthreads();   // P and V all visible

        // ---- phase 4: O += P V  (warp = 32 rows x 64 cols; V frags shared over mt) ----
#pragma unroll
        for (int kk = 0; kk < 8; ++kk) {
            float2 pa[2], pb2[2];
#pragma unroll
            for (int mt = 0; mt < 2; ++mt) {
                const float* pr = PB + (mh * 32 + mt * 16 + g) * PP + kk * 8 + 2 * tg;
                pa[mt]  = *reinterpret_cast<const float2*>(pr);           // a0,a2
                pb2[mt] = *reinterpret_cast<const float2*>(pr + 8 * PP);  // a1,a3
            }
            const float* vrow = Vsm + (kk * 8 + tg) * VPW + cs * 64 + g;
#pragma unroll
            for (int nt = 0; nt < 8; ++nt) {
                float b0 = vrow[nt * 8];              // raw fp32 -> HW truncation
                float b1 = vrow[nt * 8 + 4 * VPW];
#pragma unroll
                for (int mt = 0; mt < 2; ++mt) {
                    mma8(o[mt * 8 + nt][0], o[mt * 8 + nt][1],
                         o[mt * 8 + nt][2], o[mt * 8 + nt][3],
                         pa[mt].x, pb2[mt].x, pa[mt].y, pb2[mt].y, b0, b1);
                }
            }
        }
    }

    // ---- epilogue: reduce l, broadcast inverses, out = O * inv ----
    l0 += __shfl_xor_sync(0xffffffffu, l0, 1);
    l0 += __shfl_xor_sync(0xffffffffu, l0, 2);
    l1 += __shfl_xor_sync(0xffffffffu, l1, 1);
    l1 += __shfl_xor_sync(0xffffffffu, l1, 2);
    __syncthreads();                       // PB/SB free
    if (tg == 0) {
        SB[wq * 64 + rb + g]     = l0;
        SB[wq * 64 + rb + g + 8] = l1;
    }
    __syncthreads();
    if (wq == 0) {
        float s0 = 0.f, s1 = 0.f;
#pragma unroll
        for (int q = 0; q < 4; ++q) {
            s0 += SB[q * 64 + rb + g];
            s1 += SB[q * 64 + rb + g + 8];
        }
        if (tg == 0) {
            SB[256 + rb + g]     = 1.0f / s0;
            SB[256 + rb + g + 8] = 1.0f / s1;
        }
    }
    __syncthreads();
#pragma unroll
    for (int mt = 0; mt < 2; ++mt) {
        int r0 = mh * 32 + mt * 16 + g;
        int r1 = r0 + 8;
        float invA = SB[256 + r0];
        float invB = SB[256 + r1];
#pragma unroll
        for (int nt = 0; nt < 8; ++nt) {
            int col = cs * 64 + nt * 8 + 2 * tg;
            *reinterpret_cast<float2*>(Og + (size_t)r0 * D_ + col) =
                make_float2(o[mt * 8 + nt][0] * invA, o[mt * 8 + nt][1] * invA);
            *reinterpret_cast<float2*>(Og + (size_t)r1 * D_ + col) =
                make_float2(o[mt * 8 + nt][2] * invB, o[mt * 8 + nt][3] * invB);
        }
    }
}

extern "C" void kernel_launch(void* const* d_in, const int* in_sizes, int n_in,
                              void* d_out, int out_size) {
    (void)in_sizes; (void)n_in; (void)out_size;
    const float* Q = (const float*)d_in[0];
    const float* K = (const float*)d_in[1];
    const float* V = (const float*)d_in[2];
    float* O = (float*)d_out;

    const size_t smem = (size_t)(BM * VPW + 4 * BM * QP + BM * PP + 512) * sizeof(float); // 227328
    cudaFuncSetAttribute(attn_tf32_kernel,
                         cudaFuncAttributeMaxDynamicSharedMemorySize, (int)smem);

    attn_tf32_kernel<<<S_ / BM * B_, NT, smem>>>(Q, K, V, O);
}